// round 1
// baseline (speedup 1.0000x reference)
#include <cuda_runtime.h>
#include <cuda_bf16.h>
#include <mma.h>

using namespace nvcuda;
using bf16 = __nv_bfloat16;

// Problem dims (fixed by the reference)
constexpr int B_  = 2;
constexpr int N_  = 2048;
constexpr int D_  = 1024;
constexpr int H_  = 8;
constexpr int DK_ = 128;
constexpr int DV_ = 1024;
constexpr int HDK = H_ * DK_;   // 1024
constexpr int HDV = H_ * DV_;   // 8192
constexpr int HN  = H_ * N_;    // 16384

// GEMM tiling
constexpr int BM = 128, BN = 128, BK = 32;

// ---------------- scratch (__device__ globals; no runtime allocation) ------------
__device__ bf16 g_xb [(size_t)B_ * N_ * D_];     //  8 MB
__device__ bf16 g_wqb[(size_t)H_ * DK_ * D_];    //  2 MB
__device__ bf16 g_wkb[(size_t)H_ * DK_ * D_];    //  2 MB
__device__ bf16 g_wvb[(size_t)H_ * DV_ * D_];    // 16 MB
__device__ bf16 g_Q  [(size_t)B_ * N_ * HDK];    //  8 MB   layout [B][N][H*DK]
__device__ bf16 g_K  [(size_t)B_ * N_ * HDK];    //  8 MB   layout [B][N][H*DK]
__device__ bf16 g_V  [(size_t)B_ * N_ * HDV];    // 64 MB   layout [B][N][H*DV]
__device__ bf16 g_sim[(size_t)B_ * N_ * HN];     // 128 MB  layout [B][N][H*N]

// ---------------- fragment types -------------------------------------------------
using FragA  = wmma::fragment<wmma::matrix_a, 16, 16, 16, bf16, wmma::row_major>;
using FragBc = wmma::fragment<wmma::matrix_b, 16, 16, 16, bf16, wmma::col_major>;
using FragBr = wmma::fragment<wmma::matrix_b, 16, 16, 16, bf16, wmma::row_major>;
using FragC  = wmma::fragment<wmma::accumulator, 16, 16, 16, float>;

// ---------------- smem tile loaders ----------------------------------------------
// Load 128 rows x 32 cols (row-major gmem, leading dim ld) into S[128][40].
__device__ __forceinline__ void load_128x32(bf16 (*S)[BK + 8], const bf16* g, int ld, int tid) {
#pragma unroll
    for (int i = 0; i < 2; ++i) {
        int u = tid + i * 256;
        int r = u >> 2;
        int c = (u & 3) * 8;
        *reinterpret_cast<uint4*>(&S[r][c]) =
            *reinterpret_cast<const uint4*>(g + (size_t)r * ld + c);
    }
}

// Load 32 rows(k) x 128 cols(n) (row-major gmem, leading dim ld) into S[32][136].
__device__ __forceinline__ void load_32x128(bf16 (*S)[BN + 8], const bf16* g, int ld, int tid) {
#pragma unroll
    for (int i = 0; i < 2; ++i) {
        int u = tid + i * 256;
        int r = u >> 4;
        int c = (u & 15) * 8;
        *reinterpret_cast<uint4*>(&S[r][c]) =
            *reinterpret_cast<const uint4*>(g + (size_t)r * ld + c);
    }
}

// ---------------- MMA micro-steps -------------------------------------------------
// acc += As(128x32) * Bs^T  with Bs stored [n][k] (i.e. B col-major view)
__device__ __forceinline__ void mma_col(FragC acc[2][4],
                                        const bf16 (*As)[BK + 8],
                                        const bf16 (*Bs)[BK + 8],
                                        int wm, int wn) {
#pragma unroll
    for (int ks = 0; ks < BK; ks += 16) {
        FragA a[2];
        wmma::load_matrix_sync(a[0], &As[wm * 32][ks],      BK + 8);
        wmma::load_matrix_sync(a[1], &As[wm * 32 + 16][ks], BK + 8);
#pragma unroll
        for (int j = 0; j < 4; ++j) {
            FragBc b;
            wmma::load_matrix_sync(b, &Bs[wn * 64 + j * 16][ks], BK + 8);
            wmma::mma_sync(acc[0][j], a[0], b, acc[0][j]);
            wmma::mma_sync(acc[1][j], a[1], b, acc[1][j]);
        }
    }
}

// acc += As(128x32) * Bs  with Bs stored [k][n] (row-major B)
__device__ __forceinline__ void mma_row(FragC acc[2][4],
                                        const bf16 (*As)[BK + 8],
                                        const bf16 (*Bs)[BN + 8],
                                        int wm, int wn) {
#pragma unroll
    for (int ks = 0; ks < BK; ks += 16) {
        FragA a[2];
        wmma::load_matrix_sync(a[0], &As[wm * 32][ks],      BK + 8);
        wmma::load_matrix_sync(a[1], &As[wm * 32 + 16][ks], BK + 8);
#pragma unroll
        for (int j = 0; j < 4; ++j) {
            FragBr b;
            wmma::load_matrix_sync(b, &Bs[ks][wn * 64 + j * 16], BN + 8);
            wmma::mma_sync(acc[0][j], a[0], b, acc[0][j]);
            wmma::mma_sync(acc[1][j], a[1], b, acc[1][j]);
        }
    }
}

// ---------------- kernel 0: fp32 -> bf16 convert ----------------------------------
__global__ void f2bf_kernel(const float4* __restrict__ in,
                            __nv_bfloat162* __restrict__ out, int n4) {
    int i = blockIdx.x * blockDim.x + threadIdx.x;
    if (i < n4) {
        float4 v = in[i];
        out[2 * i]     = __floats2bfloat162_rn(v.x, v.y);
        out[2 * i + 1] = __floats2bfloat162_rn(v.z, v.w);
    }
}

// ---------------- kernel 1: C[M,out] = A[M,1024] * W[out,1024]^T  (bf16 out) -------
__global__ __launch_bounds__(256) void gemm_nt_bf16(const bf16* __restrict__ A,
                                                    const bf16* __restrict__ W,
                                                    bf16* __restrict__ C, int ldc) {
    __shared__ bf16 As[BM][BK + 8];
    __shared__ bf16 Bs[BN][BK + 8];
    __shared__ float stage[8][16][20];

    int tid = threadIdx.x, wid = tid >> 5, lane = tid & 31;
    int wm = wid & 3, wn = wid >> 2;

    const bf16* Ap = A + (size_t)blockIdx.y * BM * D_;
    const bf16* Bp = W + (size_t)blockIdx.x * BN * D_;

    FragC acc[2][4];
#pragma unroll
    for (int i = 0; i < 2; ++i)
#pragma unroll
        for (int j = 0; j < 4; ++j) wmma::fill_fragment(acc[i][j], 0.0f);

    for (int kc = 0; kc < D_ / BK; ++kc) {
        load_128x32(As, Ap + kc * BK, D_, tid);
        load_128x32(Bs, Bp + kc * BK, D_, tid);
        __syncthreads();
        mma_col(acc, As, Bs, wm, wn);
        __syncthreads();
    }

    bf16* Cp = C + (size_t)(blockIdx.y * BM) * ldc + blockIdx.x * BN;
    float (*stg)[20] = stage[wid];
#pragma unroll
    for (int i = 0; i < 2; ++i)
#pragma unroll
        for (int j = 0; j < 4; ++j) {
            wmma::store_matrix_sync(&stg[0][0], acc[i][j], 20, wmma::mem_row_major);
            __syncwarp();
#pragma unroll
            for (int e = 0; e < 8; ++e) {
                int idx = lane * 8 + e;
                int r = idx >> 4, c = idx & 15;
                int gr = wm * 32 + i * 16 + r;
                int gc = wn * 64 + j * 16 + c;
                Cp[(size_t)gr * ldc + gc] = __float2bfloat16(stg[r][c]);
            }
            __syncwarp();
        }
}

// ---------------- kernel 2: causal relu scores -> sim ------------------------------
__global__ __launch_bounds__(256) void scores_kernel(const bf16* __restrict__ Q,
                                                     const bf16* __restrict__ Kx,
                                                     bf16* __restrict__ sim) {
    int mt = blockIdx.x, nt = blockIdx.y;
    int b = blockIdx.z >> 3, h = blockIdx.z & 7;
    int tid = threadIdx.x;

    bf16* out = sim + (size_t)(b * N_ + nt * BM) * HN + h * N_ + mt * BN;

    if (mt > nt) {  // fully masked tile: just write zeros
        uint4 z = make_uint4(0, 0, 0, 0);
#pragma unroll
        for (int i = 0; i < 8; ++i) {
            int u = tid + i * 256;
            int r = u >> 4, c = (u & 15) * 8;
            *reinterpret_cast<uint4*>(out + (size_t)r * HN + c) = z;
        }
        return;
    }

    __shared__ bf16 As[BM][BK + 8];
    __shared__ bf16 Bs[BN][BK + 8];
    __shared__ float stage[8][16][20];

    int wid = tid >> 5, lane = tid & 31;
    int wm = wid & 3, wn = wid >> 2;

    const bf16* Ap = Q  + (size_t)(b * N_ + nt * BM) * HDK + h * DK_;
    const bf16* Bp = Kx + (size_t)(b * N_ + mt * BN) * HDK + h * DK_;

    FragC acc[2][4];
#pragma unroll
    for (int i = 0; i < 2; ++i)
#pragma unroll
        for (int j = 0; j < 4; ++j) wmma::fill_fragment(acc[i][j], 0.0f);

#pragma unroll
    for (int kc = 0; kc < DK_ / BK; ++kc) {  // 4 chunks
        load_128x32(As, Ap + kc * BK, HDK, tid);
        load_128x32(Bs, Bp + kc * BK, HDK, tid);
        __syncthreads();
        mma_col(acc, As, Bs, wm, wn);
        __syncthreads();
    }

    const float inv_n = 1.0f / (float)N_;
    float (*stg)[20] = stage[wid];
#pragma unroll
    for (int i = 0; i < 2; ++i)
#pragma unroll
        for (int j = 0; j < 4; ++j) {
            wmma::store_matrix_sync(&stg[0][0], acc[i][j], 20, wmma::mem_row_major);
            __syncwarp();
#pragma unroll
            for (int e = 0; e < 8; ++e) {
                int idx = lane * 8 + e;
                int r = idx >> 4, c = idx & 15;
                int lr = wm * 32 + i * 16 + r;     // local n
                int lc = wn * 64 + j * 16 + c;     // local m
                int gn = nt * BM + lr;
                int gm = mt * BN + lc;
                float v = stg[r][c];
                v = (gm <= gn) ? fmaxf(v, 0.0f) * inv_n : 0.0f;
                out[(size_t)lr * HN + lc] = __float2bfloat16(v);
            }
            __syncwarp();
        }
}

// ---------------- kernel 3: out = x + sim @ V (causal K bound, concat heads) -------
__global__ __launch_bounds__(256) void av_kernel(const bf16* __restrict__ sim,
                                                 const bf16* __restrict__ V,
                                                 const float* __restrict__ x,
                                                 float* __restrict__ out) {
    int vt = blockIdx.x;            // 0..7 over DV
    int tn = 15 - blockIdx.y;       // heavy tiles first
    int b  = blockIdx.z;

    __shared__ bf16 As[BM][BK + 8];
    __shared__ bf16 Bs[BK][BN + 8];
    __shared__ float stage[8][16][20];

    int tid = threadIdx.x, wid = tid >> 5, lane = tid & 31;
    int wm = wid & 3, wn = wid >> 2;

    const bf16* Ab = sim + (size_t)(b * N_ + tn * BM) * HN;
    const bf16* Vb = V   + (size_t)b * N_ * HDV + vt * BN;

    FragC acc[2][4];
#pragma unroll
    for (int i = 0; i < 2; ++i)
#pragma unroll
        for (int j = 0; j < 4; ++j) wmma::fill_fragment(acc[i][j], 0.0f);

    int nch = (tn + 1) * (BM / BK);  // causal: only m <= tn*128+127 contributes
    for (int h = 0; h < H_; ++h) {
        const bf16* Ah = Ab + h * N_;
        const bf16* Vh = Vb + h * DV_;
        for (int kc = 0; kc < nch; ++kc) {
            load_128x32(As, Ah + kc * BK, HN, tid);
            load_32x128(Bs, Vh + (size_t)kc * BK * HDV, HDV, tid);
            __syncthreads();
            mma_row(acc, As, Bs, wm, wn);
            __syncthreads();
        }
    }

    size_t rowbase = (size_t)(b * N_ + tn * BM);
    float (*stg)[20] = stage[wid];
#pragma unroll
    for (int i = 0; i < 2; ++i)
#pragma unroll
        for (int j = 0; j < 4; ++j) {
            wmma::store_matrix_sync(&stg[0][0], acc[i][j], 20, wmma::mem_row_major);
            __syncwarp();
#pragma unroll
            for (int e = 0; e < 8; ++e) {
                int idx = lane * 8 + e;
                int r = idx >> 4, c = idx & 15;
                int gr = wm * 32 + i * 16 + r;
                int gc = wn * 64 + j * 16 + c;
                size_t o = (rowbase + gr) * (size_t)DV_ + vt * BN + gc;
                out[o] = x[o] + stg[r][c];
            }
            __syncwarp();
        }
}

// ---------------- host launcher ---------------------------------------------------
static void conv_launch(const float* src, bf16* dst, int n) {
    int n4 = n / 4;
    f2bf_kernel<<<(n4 + 255) / 256, 256>>>(
        reinterpret_cast<const float4*>(src),
        reinterpret_cast<__nv_bfloat162*>(dst), n4);
}

extern "C" void kernel_launch(void* const* d_in, const int* in_sizes, int n_in,
                              void* d_out, int out_size) {
    (void)in_sizes; (void)n_in; (void)out_size;
    const float* x  = (const float*)d_in[0];
    const float* Wq = (const float*)d_in[1];
    const float* Wk = (const float*)d_in[2];
    const float* Wv = (const float*)d_in[3];

    bf16 *xb, *wqb, *wkb, *wvb, *Q, *K, *V, *sim;
    cudaGetSymbolAddress((void**)&xb,  g_xb);
    cudaGetSymbolAddress((void**)&wqb, g_wqb);
    cudaGetSymbolAddress((void**)&wkb, g_wkb);
    cudaGetSymbolAddress((void**)&wvb, g_wvb);
    cudaGetSymbolAddress((void**)&Q,   g_Q);
    cudaGetSymbolAddress((void**)&K,   g_K);
    cudaGetSymbolAddress((void**)&V,   g_V);
    cudaGetSymbolAddress((void**)&sim, g_sim);

    conv_launch(x,  xb,  B_ * N_ * D_);
    conv_launch(Wq, wqb, H_ * DK_ * D_);
    conv_launch(Wk, wkb, H_ * DK_ * D_);
    conv_launch(Wv, wvb, H_ * DV_ * D_);

    // Q/K/V projections: [4096,1024] x [out,1024]^T
    gemm_nt_bf16<<<dim3(HDK / BN, (B_ * N_) / BM), 256>>>(xb, wqb, Q, HDK);
    gemm_nt_bf16<<<dim3(HDK / BN, (B_ * N_) / BM), 256>>>(xb, wkb, K, HDK);
    gemm_nt_bf16<<<dim3(HDV / BN, (B_ * N_) / BM), 256>>>(xb, wvb, V, HDV);

    // causal relu(QK^T)/N -> sim
    scores_kernel<<<dim3(N_ / BN, N_ / BM, B_ * H_), 256>>>(Q, K, sim);

    // out = x + sim @ V
    av_kernel<<<dim3(DV_ / BN, N_ / BM, B_), 256>>>(sim, V, x, (float*)d_out);
}

// round 3
// speedup vs baseline: 1.6723x; 1.6723x over previous
#include <cuda_runtime.h>
#include <cuda_bf16.h>
#include <mma.h>
#include <cstdint>

using namespace nvcuda;
using bf16 = __nv_bfloat16;

// ---------------- problem dims --------------------------------------------------
constexpr int B_  = 2;
constexpr int N_  = 2048;
constexpr int D_  = 1024;
constexpr int H_  = 8;
constexpr int DK_ = 128;
constexpr int DV_ = 1024;
constexpr int HDK = H_ * DK_;    // 1024
constexpr int HDV = H_ * DV_;    // 8192
constexpr int HN  = H_ * N_;     // 16384

// ---------------- pipeline config -----------------------------------------------
constexpr int S_ = 4;                     // stage buffers (3 in flight)
constexpr int A_STRIDE = 40;              // bf16 elems per A-stage row (128 rows)
constexpr int B_ROW_STRIDE = 136;         // bf16 elems per row-major B stage row (32 rows)
constexpr int STAGE_BYTES = 20480;        // A tile 10240 + B tile 10240
constexpr int DSMEM = S_ * STAGE_BYTES;   // 81920 (also reused as fp32 epilogue stage)
constexpr int EP_STRIDE = 136;            // fp32 stage stride (128x136 floats = 69632 B)

// ---------------- scratch (__device__ globals) ----------------------------------
__device__ bf16 g_xb [(size_t)B_ * N_ * D_];     //  8 MB
__device__ bf16 g_wqb[(size_t)H_ * DK_ * D_];    //  2 MB
__device__ bf16 g_wkb[(size_t)H_ * DK_ * D_];    //  2 MB
__device__ bf16 g_wvb[(size_t)H_ * DV_ * D_];    // 16 MB
__device__ bf16 g_Q  [(size_t)B_ * N_ * HDK];    //  8 MB  [B*N][H*DK]
__device__ bf16 g_K  [(size_t)B_ * N_ * HDK];    //  8 MB  [B*N][H*DK]
__device__ bf16 g_V  [(size_t)B_ * N_ * HDV];    // 64 MB  [B*N][H*DV]
__device__ bf16 g_sim[(size_t)B_ * N_ * HN];     // 128 MB [B*N][H*N] (lower-tri only)

// ---------------- fragment types -------------------------------------------------
using FragA  = wmma::fragment<wmma::matrix_a, 16, 16, 16, bf16, wmma::row_major>;
using FragBc = wmma::fragment<wmma::matrix_b, 16, 16, 16, bf16, wmma::col_major>;
using FragBr = wmma::fragment<wmma::matrix_b, 16, 16, 16, bf16, wmma::row_major>;
using FragC  = wmma::fragment<wmma::accumulator, 16, 16, 16, float>;

// ---------------- cp.async helpers -----------------------------------------------
__device__ __forceinline__ uint32_t smem_u32(const void* p) {
    uint32_t a;
    asm("{ .reg .u64 t; cvta.to.shared.u64 t, %1; cvt.u32.u64 %0, t; }"
        : "=r"(a) : "l"(p));
    return a;
}
__device__ __forceinline__ void cp16(uint32_t dst, const void* src) {
    asm volatile("cp.async.cg.shared.global [%0], [%1], 16;"
                 :: "r"(dst), "l"(__cvta_generic_to_global(src)));
}
__device__ __forceinline__ void cp_commit() {
    asm volatile("cp.async.commit_group;" ::: "memory");
}
__device__ __forceinline__ void cp_wait2() {
    asm volatile("cp.async.wait_group 2;" ::: "memory");
}

// A stage: 128 rows x 32 cols K-major (row stride 40 elems = 80 B)
__device__ __forceinline__ void ld_A(uint32_t sdst, const bf16* g, int ld, int tid) {
#pragma unroll
    for (int i = 0; i < 2; ++i) {
        int u = tid + i * 256;
        int r = u >> 2, c = (u & 3) * 8;
        cp16(sdst + (uint32_t)(r * (A_STRIDE * 2) + c * 2),
             g + (size_t)r * ld + c);
    }
}
// B stage (NT form): 128 rows x 32 cols K-major (same shape as A)
__device__ __forceinline__ void ld_Bcol(uint32_t sdst, const bf16* g, int ld, int tid) {
    ld_A(sdst, g, ld, tid);
}
// B stage (row form, AV): 32 rows(k) x 128 cols(n) (row stride 136 elems = 272 B)
__device__ __forceinline__ void ld_Brow(uint32_t sdst, const bf16* g, int ld, int tid) {
#pragma unroll
    for (int i = 0; i < 2; ++i) {
        int u = tid + i * 256;
        int r = u >> 4, c = (u & 15) * 8;
        cp16(sdst + (uint32_t)(r * (B_ROW_STRIDE * 2) + c * 2),
             g + (size_t)r * ld + c);
    }
}

// ---------------- MMA micro-steps -------------------------------------------------
__device__ __forceinline__ void mma_col(FragC acc[2][4], const bf16* As, const bf16* Bs,
                                        int wm, int wn) {
#pragma unroll
    for (int ks = 0; ks < 32; ks += 16) {
        FragA a[2];
        wmma::load_matrix_sync(a[0], As + (wm * 32) * A_STRIDE + ks,      A_STRIDE);
        wmma::load_matrix_sync(a[1], As + (wm * 32 + 16) * A_STRIDE + ks, A_STRIDE);
#pragma unroll
        for (int j = 0; j < 4; ++j) {
            FragBc b;
            wmma::load_matrix_sync(b, Bs + (wn * 64 + j * 16) * A_STRIDE + ks, A_STRIDE);
            wmma::mma_sync(acc[0][j], a[0], b, acc[0][j]);
            wmma::mma_sync(acc[1][j], a[1], b, acc[1][j]);
        }
    }
}
__device__ __forceinline__ void mma_row(FragC acc[2][4], const bf16* As, const bf16* Bs,
                                        int wm, int wn) {
#pragma unroll
    for (int ks = 0; ks < 32; ks += 16) {
        FragA a[2];
        wmma::load_matrix_sync(a[0], As + (wm * 32) * A_STRIDE + ks,      A_STRIDE);
        wmma::load_matrix_sync(a[1], As + (wm * 32 + 16) * A_STRIDE + ks, A_STRIDE);
#pragma unroll
        for (int j = 0; j < 4; ++j) {
            FragBr b;
            wmma::load_matrix_sync(b, Bs + ks * B_ROW_STRIDE + wn * 64 + j * 16, B_ROW_STRIDE);
            wmma::mma_sync(acc[0][j], a[0], b, acc[0][j]);
            wmma::mma_sync(acc[1][j], a[1], b, acc[1][j]);
        }
    }
}

// ---------------- pipelined mainloops ---------------------------------------------
// NT: A rows K-major (lda), B rows K-major (ldb); nk chunks of K=32.
__device__ __forceinline__ void loop_nt(FragC acc[2][4], char* dsm,
                                        const bf16* A, int lda,
                                        const bf16* Bp, int ldb,
                                        int nk, int tid, int wm, int wn) {
    uint32_t sb = smem_u32(dsm);
#pragma unroll
    for (int s = 0; s < 3; ++s) {
        if (s < nk) {
            ld_A   (sb + s * STAGE_BYTES,         A  + s * 32, lda, tid);
            ld_Bcol(sb + s * STAGE_BYTES + 10240, Bp + s * 32, ldb, tid);
        }
        cp_commit();
    }
    for (int i = 0; i < nk; ++i) {
        cp_wait2();
        __syncthreads();
        int ci = i + 3;
        if (ci < nk) {
            uint32_t st = sb + (uint32_t)(ci & 3) * STAGE_BYTES;
            ld_A   (st,         A  + ci * 32, lda, tid);
            ld_Bcol(st + 10240, Bp + ci * 32, ldb, tid);
        }
        cp_commit();
        const bf16* As = reinterpret_cast<const bf16*>(dsm + (i & 3) * STAGE_BYTES);
        mma_col(acc, As, As + 10240 / 2, wm, wn);
    }
    __syncthreads();
}

// AV: A = sim row-block (cols h*N_ + kc*32), B = V rows [k][n]; nkh chunks/head.
__device__ __forceinline__ void loop_av(FragC acc[2][4], char* dsm,
                                        const bf16* Arow, const bf16* Vb,
                                        int nkh, int tid, int wm, int wn) {
    uint32_t sb = smem_u32(dsm);
    const int nk = nkh * H_;
#pragma unroll
    for (int s = 0; s < 3; ++s) {
        {   // nk >= 8 always (nkh >= 4)
            int h = s / nkh, kc = s - h * nkh;
            ld_A   (sb + s * STAGE_BYTES,         Arow + h * N_ + kc * 32, HN, tid);
            ld_Brow(sb + s * STAGE_BYTES + 10240, Vb + (size_t)(kc * 32) * HDV + h * DV_,
                    HDV, tid);
        }
        cp_commit();
    }
    for (int i = 0; i < nk; ++i) {
        cp_wait2();
        __syncthreads();
        int ci = i + 3;
        if (ci < nk) {
            int h = ci / nkh, kc = ci - h * nkh;
            uint32_t st = sb + (uint32_t)(ci & 3) * STAGE_BYTES;
            ld_A   (st,         Arow + h * N_ + kc * 32, HN, tid);
            ld_Brow(st + 10240, Vb + (size_t)(kc * 32) * HDV + h * DV_, HDV, tid);
        }
        cp_commit();
        const bf16* As = reinterpret_cast<const bf16*>(dsm + (i & 3) * STAGE_BYTES);
        mma_row(acc, As, As + 10240 / 2, wm, wn);
    }
    __syncthreads();
}

// ---------------- epilogues -------------------------------------------------------
__device__ __forceinline__ void stage_acc(FragC acc[2][4], float* stg, int wm, int wn) {
#pragma unroll
    for (int i = 0; i < 2; ++i)
#pragma unroll
        for (int j = 0; j < 4; ++j)
            wmma::store_matrix_sync(stg + (wm * 32 + i * 16) * EP_STRIDE + wn * 64 + j * 16,
                                    acc[i][j], EP_STRIDE, wmma::mem_row_major);
}

// MODE 0: plain bf16 store. MODE 1: causal relu/N bf16 store.
template <int MODE>
__device__ __forceinline__ void ep_bf16(FragC acc[2][4], char* dsm, bf16* C, int ldc,
                                        int q0, int m0, int tid, int wm, int wn) {
    float* stg = reinterpret_cast<float*>(dsm);
    stage_acc(acc, stg, wm, wn);
    __syncthreads();
    const float inv_n = 1.0f / (float)N_;
#pragma unroll
    for (int it = 0; it < 8; ++it) {
        int idx = it * 256 + tid;
        int r = idx >> 4, cv = idx & 15;
        const float* p = stg + r * EP_STRIDE + cv * 8;
        union { bf16 v[8]; uint4 u4; } pk;
#pragma unroll
        for (int e = 0; e < 8; ++e) {
            float v = p[e];
            if (MODE == 1) {
                int gm = m0 + cv * 8 + e;
                v = (gm <= q0 + r) ? fmaxf(v, 0.0f) * inv_n : 0.0f;
            }
            pk.v[e] = __float2bfloat16(v);
        }
        *reinterpret_cast<uint4*>(C + (size_t)r * ldc + cv * 8) = pk.u4;
    }
    __syncthreads();
}

__device__ __forceinline__ void ep_resid(FragC acc[2][4], char* dsm, float* out,
                                         const float* x, size_t rowbase, int colbase,
                                         int tid, int wm, int wn) {
    float* stg = reinterpret_cast<float*>(dsm);
    stage_acc(acc, stg, wm, wn);
    __syncthreads();
#pragma unroll
    for (int it = 0; it < 16; ++it) {
        int idx = it * 256 + tid;
        int r = idx >> 5, cv = idx & 31;
        size_t o = (rowbase + r) * (size_t)DV_ + colbase + cv * 4;
        float4 xv = *reinterpret_cast<const float4*>(x + o);
        const float* p = stg + r * EP_STRIDE + cv * 4;
        float4 ov = make_float4(xv.x + p[0], xv.y + p[1], xv.z + p[2], xv.w + p[3]);
        *reinterpret_cast<float4*>(out + o) = ov;
    }
    __syncthreads();
}

// ---------------- kernels ---------------------------------------------------------
__global__ void f2bf_kernel(const float4* __restrict__ in,
                            __nv_bfloat162* __restrict__ out, int n4) {
    int i = blockIdx.x * blockDim.x + threadIdx.x;
    if (i < n4) {
        float4 v = in[i];
        out[2 * i]     = __floats2bfloat162_rn(v.x, v.y);
        out[2 * i + 1] = __floats2bfloat162_rn(v.z, v.w);
    }
}

__global__ __launch_bounds__(256) void k_proj(const bf16* __restrict__ A0,
                                              const bf16* __restrict__ W,
                                              bf16* __restrict__ C0, int ldc) {
    extern __shared__ char dsm[];
    int tid = threadIdx.x, wid = tid >> 5;
    int wm = wid & 3, wn = wid >> 2;
    const bf16* A  = A0 + (size_t)blockIdx.y * 128 * D_;
    const bf16* Bp = W  + (size_t)blockIdx.x * 128 * D_;
    bf16* C = C0 + (size_t)(blockIdx.y * 128) * ldc + blockIdx.x * 128;

    FragC acc[2][4];
#pragma unroll
    for (int i = 0; i < 2; ++i)
#pragma unroll
        for (int j = 0; j < 4; ++j) wmma::fill_fragment(acc[i][j], 0.0f);

    loop_nt(acc, dsm, A, D_, Bp, D_, D_ / 32, tid, wm, wn);
    ep_bf16<0>(acc, dsm, C, ldc, 0, 0, tid, wm, wn);
}

__global__ __launch_bounds__(256) void k_scores(const bf16* __restrict__ Q,
                                                const bf16* __restrict__ Kx,
                                                bf16* __restrict__ sim) {
    int mt = blockIdx.x, nt = blockIdx.y;
    if (mt > nt) return;                       // upper tiles never read by AV
    int b = blockIdx.z >> 3, h = blockIdx.z & 7;
    extern __shared__ char dsm[];
    int tid = threadIdx.x, wid = tid >> 5;
    int wm = wid & 3, wn = wid >> 2;

    const bf16* A  = Q  + ((size_t)(b * N_ + nt * 128)) * HDK + h * DK_;
    const bf16* Bp = Kx + ((size_t)(b * N_ + mt * 128)) * HDK + h * DK_;
    bf16* C = sim + ((size_t)(b * N_ + nt * 128)) * HN + (size_t)h * N_ + mt * 128;

    FragC acc[2][4];
#pragma unroll
    for (int i = 0; i < 2; ++i)
#pragma unroll
        for (int j = 0; j < 4; ++j) wmma::fill_fragment(acc[i][j], 0.0f);

    loop_nt(acc, dsm, A, HDK, Bp, HDK, DK_ / 32, tid, wm, wn);
    ep_bf16<1>(acc, dsm, C, HN, nt * 128, mt * 128, tid, wm, wn);
}

// Balanced AV: block handles row tiles {15-pair, pair}: work = 17 units each.
__global__ __launch_bounds__(256) void k_av(const bf16* __restrict__ sim,
                                            const bf16* __restrict__ V,
                                            const float* __restrict__ x,
                                            float* __restrict__ out) {
    int vt = blockIdx.x, pair = blockIdx.y, b = blockIdx.z;
    extern __shared__ char dsm[];
    int tid = threadIdx.x, wid = tid >> 5;
    int wm = wid & 3, wn = wid >> 2;

    const bf16* Vb = V + (size_t)b * N_ * HDV + vt * 128;

    int tns[2] = {15 - pair, pair};           // heavy tile first
#pragma unroll
    for (int t = 0; t < 2; ++t) {
        int tn = tns[t];
        const bf16* Arow = sim + ((size_t)(b * N_ + tn * 128)) * HN;

        FragC acc[2][4];
#pragma unroll
        for (int i = 0; i < 2; ++i)
#pragma unroll
            for (int j = 0; j < 4; ++j) wmma::fill_fragment(acc[i][j], 0.0f);

        loop_av(acc, dsm, Arow, Vb, (tn + 1) * 4, tid, wm, wn);
        ep_resid(acc, dsm, out, x, (size_t)(b * N_ + tn * 128), vt * 128, tid, wm, wn);
    }
}

// ---------------- host launcher ---------------------------------------------------
static void conv_launch(const float* src, bf16* dst, int n) {
    int n4 = n / 4;
    f2bf_kernel<<<(n4 + 255) / 256, 256>>>(
        reinterpret_cast<const float4*>(src),
        reinterpret_cast<__nv_bfloat162*>(dst), n4);
}

extern "C" void kernel_launch(void* const* d_in, const int* in_sizes, int n_in,
                              void* d_out, int out_size) {
    (void)in_sizes; (void)n_in; (void)out_size;
    const float* x  = (const float*)d_in[0];
    const float* Wq = (const float*)d_in[1];
    const float* Wk = (const float*)d_in[2];
    const float* Wv = (const float*)d_in[3];

    bf16 *xb, *wqb, *wkb, *wvb, *Q, *K, *V, *sim;
    cudaGetSymbolAddress((void**)&xb,  g_xb);
    cudaGetSymbolAddress((void**)&wqb, g_wqb);
    cudaGetSymbolAddress((void**)&wkb, g_wkb);
    cudaGetSymbolAddress((void**)&wvb, g_wvb);
    cudaGetSymbolAddress((void**)&Q,   g_Q);
    cudaGetSymbolAddress((void**)&K,   g_K);
    cudaGetSymbolAddress((void**)&V,   g_V);
    cudaGetSymbolAddress((void**)&sim, g_sim);

    cudaFuncSetAttribute(k_proj,   cudaFuncAttributeMaxDynamicSharedMemorySize, DSMEM);
    cudaFuncSetAttribute(k_scores, cudaFuncAttributeMaxDynamicSharedMemorySize, DSMEM);
    cudaFuncSetAttribute(k_av,     cudaFuncAttributeMaxDynamicSharedMemorySize, DSMEM);

    conv_launch(x,  xb,  B_ * N_ * D_);
    conv_launch(Wq, wqb, H_ * DK_ * D_);
    conv_launch(Wk, wkb, H_ * DK_ * D_);
    conv_launch(Wv, wvb, H_ * DV_ * D_);

    // Q = x Wq^T, K = x Wk^T, V = x Wv^T
    k_proj<<<dim3(HDK / 128, (B_ * N_) / 128), 256, DSMEM>>>(xb, wqb, Q, HDK);
    k_proj<<<dim3(HDK / 128, (B_ * N_) / 128), 256, DSMEM>>>(xb, wkb, K, HDK);
    k_proj<<<dim3(HDV / 128, (B_ * N_) / 128), 256, DSMEM>>>(xb, wvb, V, HDV);

    // sim = causal relu(Q K^T)/N  (lower-triangle tiles only)
    k_scores<<<dim3(16, 16, 16), 256, DSMEM>>>(Q, K, sim);

    // out = x + sim V  (balanced: pair tn with 15-tn)
    k_av<<<dim3(8, 8, 2), 256, DSMEM>>>(sim, V, x, (float*)d_out);
}